// round 7
// baseline (speedup 1.0000x reference)
#include <cuda_runtime.h>
#include <math.h>

#define N_SAMPLES 262144
#define N_FLOAT4 (N_SAMPLES / 4)                  // 65536
#define N_K 128
#define N_STEPS 1024
#define K_TILE 32
#define NPAIR (K_TILE / 2)                        // 16 packed harmonic pairs
#define N_TILES (N_K / K_TILE)                    // 4
#define CHUNKS 37
#define TOTAL_BLOCKS (N_TILES * CHUNKS)           // 148 = 1 per SM
#define THREADS1 384
#define NWARPS (THREADS1 / 32)                    // 12
#define NACC (4 * K_TILE)                         // 128
#define VALS (NACC + 1)                           // 129
#define TWO_PI 6.2831855f

typedef unsigned long long u64;

// Packed f32x2 helpers (FFMA2 path — only reachable via PTX)
__device__ __forceinline__ u64 pk(float lo, float hi) {
    u64 r; asm("mov.b64 %0, {%1, %2};" : "=l"(r) : "f"(lo), "f"(hi)); return r;
}
__device__ __forceinline__ void upk(u64 v, float& lo, float& hi) {
    asm("mov.b64 {%0, %1}, %2;" : "=f"(lo), "=f"(hi) : "l"(v));
}
__device__ __forceinline__ u64 f2fma(u64 a, u64 b, u64 c) {
    u64 d; asm("fma.rn.f32x2 %0, %1, %2, %3;" : "=l"(d) : "l"(a), "l"(b), "l"(c)); return d;
}
__device__ __forceinline__ u64 f2add(u64 a, u64 b) {
    u64 d; asm("add.rn.f32x2 %0, %1, %2;" : "=l"(d) : "l"(a), "l"(b)); return d;
}

__device__ float g_scratch[N_TILES * CHUNKS * VALS];
__device__ float g_coef[N_TILES * VALS];
__device__ float g_posn[N_STEPS + 2], g_negn[N_STEPS + 2];
__device__ unsigned int g_cnt1 = 0, g_cnt2 = 0, g_cnt3 = 0;

// ---------------------------------------------------------------------------
// Single fused kernel. Grid (37 chunks, 4 tiles) = 148 blocks, exactly 1 per
// SM (__launch_bounds__(384,1)) -> all co-resident, spin barriers safe.
//
// Phase 1: Fourier reduction. Pair q packs harmonics (k0+2q, k0+2q+1) in
//   f32x2. Chebyshev 3-term recurrence P_{q+1} = t*P_q - P_{q-1}, t=2cos(2th),
//   with period-4 sign absorption R_q = sigma_q * P_q, sigma = (+,+,-,-):
//     R_{q+1} = fma(-t, R_q, R_{q-1})   for odd  q  (link uses -t)
//     R_{q+1} = fma(+t, R_q, R_{q-1})   for even q  (link uses +t)
//   One packed FMA per component per link. Pairs with q mod 4 in {2,3} get
//   their sign restored in the epilogue.
// Phase 2: 4 tile-leader blocks fold chunk partials -> g_coef
// Phase 3: all blocks: normalize coefficients + CDF steps (grid-strided)
// Phase 4: block 0 computes the AUC scalar, resets counters.
// ---------------------------------------------------------------------------
__global__ void __launch_bounds__(THREADS1, 1)
fused_kernel(const float4* __restrict__ scores4, const uint4* __restrict__ targets4,
             float* __restrict__ out)
{
    const int chunk = blockIdx.x;
    const int tile  = blockIdx.y;
    const int tid   = threadIdx.x;
    const int bid   = tile * CHUNKS + chunk;
    const int lane  = tid & 31, wid = tid >> 5;

    // ------------------ Phase 1: reduction ------------------
    u64 aTS[NPAIR], aTC[NPAIR], aPS[NPAIR], aPC[NPAIR];
#pragma unroll
    for (int p = 0; p < NPAIR; ++p) { aTS[p] = 0; aTC[p] = 0; aPS[p] = 0; aPC[p] = 0; }
    float cnt = 0.f;

    const float k0f = (float)(tile * K_TILE + 1);
    const int s4 = (chunk * N_FLOAT4) / CHUNKS;
    const int e4 = ((chunk + 1) * N_FLOAT4) / CHUNKS;

    for (int i = s4 + tid; i < e4; i += THREADS1) {
        const float4 sv = scores4[i];
        const uint4  tv = targets4[i];
        const float scs[4] = {sv.x, sv.y, sv.z, sv.w};
        const float msk[4] = {(float)tv.x, (float)tv.y, (float)tv.z, (float)tv.w};
#pragma unroll
        for (int e = 0; e < 4; ++e) {
            const float sc = scs[e];
            const float m  = msk[e];
            cnt += m;

            const float th = TWO_PI * sc;
            float s1, c1;
            __sincosf(th, &s1, &c1);
            float sA, cA;                              // harmonic k0
            __sincosf(k0f * th, &sA, &cA);
            const float sB = fmaf(sA, c1,  cA * s1);   // k0+1
            const float cB = fmaf(cA, c1, -sA * s1);
            const float s2 = 2.f * s1 * c1;            // sin/cos(2*theta)
            const float c2 = fmaf(c1, c1, -s1 * s1);
            const float sC = fmaf(sA, c2,  cA * s2);   // k0+2
            const float cC = fmaf(cA, c2, -sA * s2);
            const float sD = fmaf(sB, c2,  cB * s2);   // k0+3
            const float cD = fmaf(cB, c2, -sB * s2);
            const float t  = 2.f * c2;                 // Chebyshev t = 2cos(2th)

            u64 rs0 = pk(sA, sB), rc0 = pk(cA, cB);    // R_0 = P_0
            u64 rs1 = pk(sC, sD), rc1 = pk(cC, cD);    // R_1 = P_1
            const u64 tp  = pk(t, t);
            const u64 ntp = pk(-t, -t);
            const u64 mp  = pk(m, m);

#pragma unroll
            for (int q = 0; q < NPAIR; q += 2) {
                aTS[q]   = f2add(aTS[q],   rs0);
                aTC[q]   = f2add(aTC[q],   rc0);
                aPS[q]   = f2fma(mp, rs0, aPS[q]);
                aPC[q]   = f2fma(mp, rc0, aPC[q]);
                aTS[q+1] = f2add(aTS[q+1], rs1);
                aTC[q+1] = f2add(aTC[q+1], rc1);
                aPS[q+1] = f2fma(mp, rs1, aPS[q+1]);
                aPC[q+1] = f2fma(mp, rc1, aPC[q+1]);
                if (q + 2 < NPAIR) {
                    // link q+1 (odd): R_{q+2} = -t*R_{q+1} + R_q
                    rs0 = f2fma(ntp, rs1, rs0);
                    rc0 = f2fma(ntp, rc1, rc0);
                    // link q+2 (even): R_{q+3} = +t*R_{q+2} + R_{q+1}
                    rs1 = f2fma(tp, rs0, rs1);
                    rc1 = f2fma(tp, rc0, rc1);
                }
            }
        }
    }

    // Epilogue: warp reduce packed accs; sigma restored (q mod 4 in {2,3} -> -1)
    __shared__ float red[NWARPS][VALS];
#pragma unroll
    for (int q = 0; q < NPAIR; ++q) {
        u64 a0 = aTS[q], a1 = aTC[q], a2 = aPS[q], a3 = aPC[q];
#pragma unroll
        for (int o = 16; o > 0; o >>= 1) {
            a0 = f2add(a0, __shfl_down_sync(0xffffffffu, a0, o));
            a1 = f2add(a1, __shfl_down_sync(0xffffffffu, a1, o));
            a2 = f2add(a2, __shfl_down_sync(0xffffffffu, a2, o));
            a3 = f2add(a3, __shfl_down_sync(0xffffffffu, a3, o));
        }
        if (lane == 0) {
            const float sg = ((q & 3) >= 2) ? -1.f : 1.f;
            float lo, hi;
            upk(a0, lo, hi); red[wid][(2*q)*4 + 0] = sg*lo; red[wid][(2*q+1)*4 + 0] = sg*hi;
            upk(a1, lo, hi); red[wid][(2*q)*4 + 1] = sg*lo; red[wid][(2*q+1)*4 + 1] = sg*hi;
            upk(a2, lo, hi); red[wid][(2*q)*4 + 2] = sg*lo; red[wid][(2*q+1)*4 + 2] = sg*hi;
            upk(a3, lo, hi); red[wid][(2*q)*4 + 3] = sg*lo; red[wid][(2*q+1)*4 + 3] = sg*hi;
        }
    }
    {
        float v = cnt;
#pragma unroll
        for (int o = 16; o > 0; o >>= 1)
            v += __shfl_down_sync(0xffffffffu, v, o);
        if (lane == 0) red[wid][NACC] = v;
    }
    __syncthreads();
    if (tid < VALS) {
        float s = 0.f;
#pragma unroll
        for (int w = 0; w < NWARPS; ++w) s += red[w][tid];
        g_scratch[(tile * CHUNKS + chunk) * VALS + tid] = s;
    }

    // ------------------ Barrier 1 (all 148 arrive, all poll) ------------------
    __threadfence();
    __syncthreads();
    if (tid == 0) {
        atomicAdd(&g_cnt1, 1u);
        volatile unsigned int* p = &g_cnt1;
        while (*p < TOTAL_BLOCKS) {}
    }
    __syncthreads();
    __threadfence();

    // ------------------ Phase 2: tile leaders fold chunks ------------------
    if (chunk == 0) {
        if (tid < VALS) {
            float s = 0.f;
            const float* base = &g_scratch[tile * CHUNKS * VALS + tid];
#pragma unroll 4
            for (int c = 0; c < CHUNKS; ++c) s += base[c * VALS];
            g_coef[tile * VALS + tid] = s;
        }
        __threadfence();
        __syncthreads();
        if (tid == 0) atomicAdd(&g_cnt2, 1u);
    }
    // ------------------ Barrier 2 (4 leaders arrive, all poll) ------------------
    if (tid == 0) {
        volatile unsigned int* p = &g_cnt2;
        while (*p < N_TILES) {}
    }
    __syncthreads();
    __threadfence();

    // ------------------ Phase 3: coefficients + CDF ------------------
    __shared__ float sisp[N_K], sicp[N_K], sisn[N_K], sicn[N_K];
    if (tid < N_K) {
        const float EPS = 1.1920929e-7f;
        const int tl = tid / K_TILE, j = tid % K_TILE;
        const float tpk = TWO_PI * (float)(tid + 1);
        const float npos = g_coef[NACC];          // tile 0 count = total positives
        const float nneg = (float)N_SAMPLES - npos;

        const float tot_s = g_coef[tl * VALS + j * 4 + 0];
        const float tot_c = g_coef[tl * VALS + j * 4 + 1];
        const float pos_s = g_coef[tl * VALS + j * 4 + 2];
        const float pos_c = g_coef[tl * VALS + j * 4 + 3];

        const float ps  = (npos < EPS) ? 0.f : pos_s / fmaxf(npos, EPS);
        const float pc  = (npos < EPS) ? 0.f : pos_c / fmaxf(npos, EPS);
        const float nsn = (nneg < EPS) ? 0.f : (tot_s - pos_s) / fmaxf(nneg, EPS);
        const float ncn = (nneg < EPS) ? 0.f : (tot_c - pos_c) / fmaxf(nneg, EPS);

        sisp[tid] =  pc / tpk;
        sicp[tid] = -ps / tpk;
        sisn[tid] =  ncn / tpk;
        sicn[tid] = -nsn / tpk;
    }
    __syncthreads();

    // CDF steps: warp w handles step = bid + 148*w (w = 0..11)
    {
        const int step = bid + TOTAL_BLOCKS * wid;
        if (step < N_STEPS) {
            const float thr = (float)step / 1023.0f;
            float cdfp = 0.f, cdfn = 0.f;
#pragma unroll
            for (int i = 0; i < 4; ++i) {
                const int k = lane + i * 32;
                const float tpk = TWO_PI * (float)(k + 1);
                float s, c;
                __sincosf(thr * tpk, &s, &c);
                cdfp = fmaf(s, sisp[k], fmaf(c, sicp[k], cdfp));
                cdfn = fmaf(s, sisn[k], fmaf(c, sicn[k], cdfn));
            }
#pragma unroll
            for (int o = 16; o > 0; o >>= 1) {
                cdfp += __shfl_down_sync(0xffffffffu, cdfp, o);
                cdfn += __shfl_down_sync(0xffffffffu, cdfn, o);
            }
            if (lane == 0) {
                g_posn[step + 1] = 1.0f - 0.5f * (cdfp + 0.5f);
                g_negn[step + 1] = 1.0f - 0.5f * (cdfn + 0.5f);
            }
        }
        if (bid == 0 && tid == 0) {
            g_posn[0] = 1.0f; g_negn[0] = 1.0f;
            g_posn[N_STEPS + 1] = 0.0f; g_negn[N_STEPS + 1] = 0.0f;
        }
    }

    // ------------------ Barrier 3 (all arrive, only block 0 polls) --------------
    __threadfence();
    __syncthreads();
    if (tid == 0) atomicAdd(&g_cnt3, 1u);
    if (bid != 0) return;

    if (tid == 0) {
        volatile unsigned int* p = &g_cnt3;
        while (*p < TOTAL_BLOCKS) {}
    }
    __syncthreads();
    __threadfence();

    // ------------------ Phase 4: AUC (block 0) ------------------
    __shared__ float redA[NWARPS], redB[NWARPS];
    float tp = 0.f, tn = 0.f;
    for (int i = tid; i < N_STEPS + 1; i += THREADS1) {
        const float p0 = g_posn[i], p1 = g_posn[i + 1];
        const float q0 = g_negn[i], q1 = g_negn[i + 1];
        tp = fmaf(p0, q0 - q1, tp);
        tn = fmaf(q0, p1 - p0, tn);
    }
#pragma unroll
    for (int o = 16; o > 0; o >>= 1) {
        tp += __shfl_down_sync(0xffffffffu, tp, o);
        tn += __shfl_down_sync(0xffffffffu, tn, o);
    }
    if (lane == 0) { redA[wid] = tp; redB[wid] = tn; }
    __syncthreads();
    if (tid == 0) {
        float a = 0.f, b = 0.f;
#pragma unroll
        for (int w = 0; w < NWARPS; ++w) { a += redA[w]; b += redB[w]; }
        out[0] = 0.5f * (a + (1.0f + b));
        g_cnt1 = 0; g_cnt2 = 0; g_cnt3 = 0;       // self-reset for graph replay
    }
}

extern "C" void kernel_launch(void* const* d_in, const int* in_sizes, int n_in,
                              void* d_out, int out_size)
{
    (void)in_sizes; (void)n_in; (void)out_size;
    const float4* scores4  = (const float4*)d_in[0];
    const uint4*  targets4 = (const uint4*)d_in[1];
    float* out = (float*)d_out;

    dim3 grid(CHUNKS, N_TILES);
    fused_kernel<<<grid, THREADS1>>>(scores4, targets4, out);
}

// round 8
// speedup vs baseline: 1.2514x; 1.2514x over previous
#include <cuda_runtime.h>
#include <math.h>

#define N_SAMPLES 262144
#define N_QUADS   (N_SAMPLES / 4)                 // 65536
#define N_K       128
#define N_STEPS   1024
#define BINS      8192
#define NBLOCKS   148                             // 1 per SM, all co-resident
#define THREADS   256
#define NWARPS    (THREADS / 32)                  // 8
#define NENT      513                             // 512 coef partials + npos
#define TWO_PI    6.2831855f

typedef unsigned long long u64;

// Histogram: per bin, high 32 bits = n_total, low 32 bits = n_positive.
__device__ u64   g_hist[BINS];
// Per-block DFT partials: [block][NENT]
__device__ float g_part[NBLOCKS * NENT];
// Folded coefficients (raw sums) + npos
__device__ float g_coef[NENT];
// Normalized CDF arrays
__device__ float g_posn[N_STEPS + 2], g_negn[N_STEPS + 2];
// Spin-barrier counters (self-reset at end of each launch)
__device__ unsigned int g_bar[5] = {0, 0, 0, 0, 0};

__device__ __forceinline__ void grid_bar(unsigned int* cnt, unsigned int target, int tid)
{
    __threadfence();
    __syncthreads();
    if (tid == 0) {
        atomicAdd(cnt, 1u);
        volatile unsigned int* p = cnt;
        while (*p < target) {}
    }
    __syncthreads();
    __threadfence();
}

// ---------------------------------------------------------------------------
// Single fused kernel, 148 blocks x 256 threads (one per SM -> co-resident).
//  P0: zero histogram slice
//  P1: histogram: one packed u64 integer atomicAdd per sample (deterministic)
//  P2: 128x8192 DFT of bin counts; per-warp register accumulators,
//      fixed-order block fold -> g_part
//  P3: distributed fixed-order fold across blocks -> g_coef
//  P4: coefficients (with exact sinc bin correction) + CDF steps
//  P5: block 0: AUC scalar, counter reset
// ---------------------------------------------------------------------------
__global__ void __launch_bounds__(THREADS, 1)
fused_kernel(const float4* __restrict__ scores4, const uint4* __restrict__ targets4,
             float* __restrict__ out)
{
    const int bid  = blockIdx.x;
    const int tid  = threadIdx.x;
    const int lane = tid & 31, wid = tid >> 5;

    // ---------- P0: zero this block's histogram slice ----------
    {
        const int zs = (bid * BINS) / NBLOCKS;
        const int ze = ((bid + 1) * BINS) / NBLOCKS;
        for (int b = zs + tid; b < ze; b += THREADS) g_hist[b] = 0ull;
    }
    grid_bar(&g_bar[0], NBLOCKS, tid);

    // ---------- P1: histogram ----------
    for (int i = bid * THREADS + tid; i < N_QUADS; i += NBLOCKS * THREADS) {
        const float4 sv = scores4[i];
        const uint4  tv = targets4[i];
        const float scs[4] = {sv.x, sv.y, sv.z, sv.w};
        const unsigned ms[4] = {tv.x, tv.y, tv.z, tv.w};
#pragma unroll
        for (int e = 0; e < 4; ++e) {
            int b = (int)(scs[e] * (float)BINS);
            b = (b > BINS - 1) ? (BINS - 1) : ((b < 0) ? 0 : b);
            const u64 add = (1ull << 32) | (u64)(ms[e] ? 1u : 0u);
            atomicAdd(&g_hist[b], add);
        }
    }
    grid_bar(&g_bar[1], NBLOCKS, tid);

    // ---------- P2: DFT over this block's bins ----------
    // Lane l accumulates harmonics k = l+1+32j (j=0..3), 4 values each.
    __shared__ float spart[NWARPS][N_K][4];
    __shared__ float snp[NWARPS];

    {
        float acc[4][4];
#pragma unroll
        for (int j = 0; j < 4; ++j)
#pragma unroll
            for (int c = 0; c < 4; ++c) acc[j][c] = 0.f;
        float npw = 0.f;

        const int bs = (bid * BINS) / NBLOCKS;
        const int be = ((bid + 1) * BINS) / NBLOCKS;
        for (int bin = bs + wid; bin < be; bin += NWARPS) {
            const u64 h = g_hist[bin];
            const float nt = (float)(unsigned)(h >> 32);
            const float np = (float)(unsigned)(h & 0xffffffffu);
            npw += (lane == 0) ? np : 0.f;
            const int tb = 2 * bin + 1;               // theta_c = 2*pi*tb/16384
#pragma unroll
            for (int j = 0; j < 4; ++j) {
                const int k = 1 + lane + 32 * j;
                const int q = (k * tb) & 16383;       // exact angle mod 2*pi
                const float ang = (float)q * (TWO_PI / 16384.0f);
                float s, c;
                __sincosf(ang, &s, &c);
                acc[j][0] = fmaf(nt, s, acc[j][0]);
                acc[j][1] = fmaf(nt, c, acc[j][1]);
                acc[j][2] = fmaf(np, s, acc[j][2]);
                acc[j][3] = fmaf(np, c, acc[j][3]);
            }
        }
#pragma unroll
        for (int j = 0; j < 4; ++j) {
            const int kk = lane + 32 * j;             // k-1
#pragma unroll
            for (int c = 0; c < 4; ++c) spart[wid][kk][c] = acc[j][c];
        }
        if (lane == 0) snp[wid] = npw;
    }
    __syncthreads();

    // Fixed-order fold of the 8 warps -> g_part[bid]
    {
        for (int e = tid; e < 512; e += THREADS) {
            const int kk = e >> 2, c = e & 3;
            float s = 0.f;
#pragma unroll
            for (int w = 0; w < NWARPS; ++w) s += spart[w][kk][c];
            g_part[bid * NENT + e] = s;
        }
        if (tid == 0) {
            float s = 0.f;
#pragma unroll
            for (int w = 0; w < NWARPS; ++w) s += snp[w];
            g_part[bid * NENT + 512] = s;
        }
    }
    grid_bar(&g_bar[2], NBLOCKS, tid);

    // ---------- P3: distributed fold across blocks -> g_coef ----------
    // Entry e handled by block (e % 148), warp (e / 148). Fixed-order lanes+tree.
    {
        const int e = bid + NBLOCKS * wid;
        if (wid < 4 && e < NENT) {
            float s = 0.f;
            for (int b = lane; b < NBLOCKS; b += 32)
                s += g_part[b * NENT + e];
#pragma unroll
            for (int o = 16; o > 0; o >>= 1)
                s += __shfl_down_sync(0xffffffffu, s, o);
            if (lane == 0) g_coef[e] = s;
        }
    }
    grid_bar(&g_bar[3], NBLOCKS, tid);

    // ---------- P4: coefficients + CDF ----------
    __shared__ float sisp[N_K], sicp[N_K], sisn[N_K], sicn[N_K];
    if (tid < N_K) {
        const float EPS = 1.1920929e-7f;
        const int k = tid + 1;
        const float tpk = TWO_PI * (float)k;
        const float npos = g_coef[512];
        const float nneg = (float)N_SAMPLES - npos;

        // sinc correction: E[sin(k*theta) | uniform bin] = sinc(k*w/2)*sin(k*theta_c)
        const float x = (float)k * (3.14159265358979f / (float)BINS);
        const float snc = __sinf(x) / x;

        const float St = g_coef[tid * 4 + 0];
        const float Ct = g_coef[tid * 4 + 1];
        const float Sp = g_coef[tid * 4 + 2];
        const float Cp = g_coef[tid * 4 + 3];

        const float ps  = (npos < EPS) ? 0.f : (Sp * snc) / fmaxf(npos, EPS);
        const float pc  = (npos < EPS) ? 0.f : (Cp * snc) / fmaxf(npos, EPS);
        const float nsn = (nneg < EPS) ? 0.f : ((St - Sp) * snc) / fmaxf(nneg, EPS);
        const float ncn = (nneg < EPS) ? 0.f : ((Ct - Cp) * snc) / fmaxf(nneg, EPS);

        sisp[tid] =  pc / tpk;
        sicp[tid] = -ps / tpk;
        sisn[tid] =  ncn / tpk;
        sicn[tid] = -nsn / tpk;
    }
    __syncthreads();

    // CDF: warp w of block bid handles step = bid + 148*w
    {
        const int step = bid + NBLOCKS * wid;
        if (step < N_STEPS) {
            const float thr = (float)step / 1023.0f;
            float cdfp = 0.f, cdfn = 0.f;
#pragma unroll
            for (int i = 0; i < 4; ++i) {
                const int k = lane + i * 32;
                const float tpk = TWO_PI * (float)(k + 1);
                float s, c;
                __sincosf(thr * tpk, &s, &c);
                cdfp = fmaf(s, sisp[k], fmaf(c, sicp[k], cdfp));
                cdfn = fmaf(s, sisn[k], fmaf(c, sicn[k], cdfn));
            }
#pragma unroll
            for (int o = 16; o > 0; o >>= 1) {
                cdfp += __shfl_down_sync(0xffffffffu, cdfp, o);
                cdfn += __shfl_down_sync(0xffffffffu, cdfn, o);
            }
            if (lane == 0) {
                g_posn[step + 1] = 1.0f - 0.5f * (cdfp + 0.5f);
                g_negn[step + 1] = 1.0f - 0.5f * (cdfn + 0.5f);
            }
        }
        if (bid == 0 && tid == 0) {
            g_posn[0] = 1.0f; g_negn[0] = 1.0f;
            g_posn[N_STEPS + 1] = 0.0f; g_negn[N_STEPS + 1] = 0.0f;
        }
    }

    // ---------- Barrier 4: all arrive; only block 0 proceeds ----------
    __threadfence();
    __syncthreads();
    if (tid == 0) atomicAdd(&g_bar[4], 1u);
    if (bid != 0) return;
    if (tid == 0) {
        volatile unsigned int* p = &g_bar[4];
        while (*p < NBLOCKS) {}
    }
    __syncthreads();
    __threadfence();

    // ---------- P5: AUC (block 0) ----------
    __shared__ float redA[NWARPS], redB[NWARPS];
    float tp = 0.f, tn = 0.f;
    for (int i = tid; i < N_STEPS + 1; i += THREADS) {
        const float p0 = g_posn[i], p1 = g_posn[i + 1];
        const float q0 = g_negn[i], q1 = g_negn[i + 1];
        tp = fmaf(p0, q0 - q1, tp);
        tn = fmaf(q0, p1 - p0, tn);
    }
#pragma unroll
    for (int o = 16; o > 0; o >>= 1) {
        tp += __shfl_down_sync(0xffffffffu, tp, o);
        tn += __shfl_down_sync(0xffffffffu, tn, o);
    }
    if (lane == 0) { redA[wid] = tp; redB[wid] = tn; }
    __syncthreads();
    if (tid == 0) {
        float a = 0.f, b = 0.f;
#pragma unroll
        for (int w = 0; w < NWARPS; ++w) { a += redA[w]; b += redB[w]; }
        out[0] = 0.5f * (a + (1.0f + b));
        g_bar[0] = 0; g_bar[1] = 0; g_bar[2] = 0; g_bar[3] = 0; g_bar[4] = 0;
    }
}

extern "C" void kernel_launch(void* const* d_in, const int* in_sizes, int n_in,
                              void* d_out, int out_size)
{
    (void)in_sizes; (void)n_in; (void)out_size;
    const float4* scores4  = (const float4*)d_in[0];
    const uint4*  targets4 = (const uint4*)d_in[1];
    float* out = (float*)d_out;

    fused_kernel<<<NBLOCKS, THREADS>>>(scores4, targets4, out);
}

// round 9
// speedup vs baseline: 1.5415x; 1.2318x over previous
#include <cuda_runtime.h>
#include <math.h>

#define N_SAMPLES 262144
#define N_QUADS   (N_SAMPLES / 4)                 // 65536
#define N_K       128
#define N_STEPS   1024
#define BINS      4096
#define DENOM     (2 * BINS)                      // 8192: angle = 2pi*q/DENOM
#define NBLOCKS   148                             // 1 per SM, all co-resident
#define THREADS   256
#define NWARPS    (THREADS / 32)                  // 8
#define NENT      513                             // 512 coef partials + npos
#define N_INTERVALS 1025
#define TWO_PI    6.2831855f

typedef unsigned long long u64;

// Histogram: per bin, high 32 = n_total, low 32 = n_positive. Zero-restored
// at the end of P2 every launch (and zero-initialized at load).
__device__ u64   g_hist[BINS];
// Per-block DFT partials: [block][NENT]
__device__ float g_part[NBLOCKS * NENT];
// Folded raw coefficient sums + npos
__device__ float g_coef[NENT];
// Per-block AUC partial sums
__device__ float g_aucA[NBLOCKS], g_aucB[NBLOCKS];
// Barrier / completion counters (self-reset each launch)
__device__ unsigned int g_bar[4] = {0, 0, 0, 0};

// Light grid barrier: release-add + acquire-poll (no threadfence / L1 flush).
__device__ __forceinline__ void gbar(unsigned int* cnt, unsigned int target)
{
    __syncthreads();
    if (threadIdx.x == 0) {
        unsigned int old;
        asm volatile("atom.release.gpu.global.add.u32 %0, [%1], %2;"
                     : "=r"(old) : "l"(cnt), "r"(1u) : "memory");
        unsigned int v;
        do {
            asm volatile("ld.acquire.gpu.global.u32 %0, [%1];"
                         : "=r"(v) : "l"(cnt) : "memory");
        } while (v < target);
    }
    __syncthreads();
}

// ---------------------------------------------------------------------------
// Single fused kernel, 148 blocks x 256 threads (1/SM, co-resident).
//  P1: histogram via one packed u64 atomic per sample        -> barrier A
//  P2: DFT of own bin slice -> g_part; zero own slice        -> barrier B
//  P3: distributed fixed-order fold g_part -> g_coef         -> barrier C
//  P4: per block: coefficients + <=8 CDF points (1/warp) + local partial AUC;
//      last block (counter) folds 148 partials -> out, resets counters.
// ---------------------------------------------------------------------------
__global__ void __launch_bounds__(THREADS, 1)
fused_kernel(const float4* __restrict__ scores4, const uint4* __restrict__ targets4,
             float* __restrict__ out)
{
    const int bid  = blockIdx.x;
    const int tid  = threadIdx.x;
    const int lane = tid & 31, wid = tid >> 5;

    // ---------------- P1: histogram ----------------
    {
        const int qs = (bid * N_QUADS) / NBLOCKS;
        const int qe = ((bid + 1) * N_QUADS) / NBLOCKS;
        for (int i = qs + tid; i < qe; i += THREADS) {
            const float4 sv = scores4[i];
            const uint4  tv = targets4[i];
            const float scs[4] = {sv.x, sv.y, sv.z, sv.w};
            const unsigned ms[4] = {tv.x, tv.y, tv.z, tv.w};
#pragma unroll
            for (int e = 0; e < 4; ++e) {
                int b = (int)(scs[e] * (float)BINS);
                b = (b > BINS - 1) ? (BINS - 1) : ((b < 0) ? 0 : b);
                const u64 add = (1ull << 32) | (u64)(ms[e] ? 1u : 0u);
                atomicAdd(&g_hist[b], add);
            }
        }
    }
    gbar(&g_bar[0], NBLOCKS);

    // ---------------- P2: DFT over own bin slice, then zero it ----------------
    __shared__ float spart[NWARPS][N_K][4];
    __shared__ float snp[NWARPS];
    {
        float acc[4][4];
#pragma unroll
        for (int j = 0; j < 4; ++j)
#pragma unroll
            for (int c = 0; c < 4; ++c) acc[j][c] = 0.f;
        float npw = 0.f;

        const int bs = (bid * BINS) / NBLOCKS;
        const int be = ((bid + 1) * BINS) / NBLOCKS;
        for (int bin = bs + wid; bin < be; bin += NWARPS) {
            const u64 h = g_hist[bin];
            const float nt = (float)(unsigned)(h >> 32);
            const float np = (float)(unsigned)(h & 0xffffffffu);
            npw += (lane == 0) ? np : 0.f;
            const int tb = 2 * bin + 1;               // theta_c = 2pi*tb/DENOM
#pragma unroll
            for (int j = 0; j < 4; ++j) {
                const int k = 1 + lane + 32 * j;
                const int q = (k * tb) & (DENOM - 1); // exact angle mod 2pi
                const float ang = (float)q * (TWO_PI / (float)DENOM);
                float s, c;
                __sincosf(ang, &s, &c);
                acc[j][0] = fmaf(nt, s, acc[j][0]);
                acc[j][1] = fmaf(nt, c, acc[j][1]);
                acc[j][2] = fmaf(np, s, acc[j][2]);
                acc[j][3] = fmaf(np, c, acc[j][3]);
            }
        }
#pragma unroll
        for (int j = 0; j < 4; ++j) {
            const int kk = lane + 32 * j;
#pragma unroll
            for (int c = 0; c < 4; ++c) spart[wid][kk][c] = acc[j][c];
        }
        if (lane == 0) snp[wid] = npw;

        // zero own slice (only this block ever reads it) -> restores invariant
        for (int b = bs + tid; b < be; b += THREADS) g_hist[b] = 0ull;
    }
    __syncthreads();
    {
        for (int e = tid; e < 512; e += THREADS) {
            const int kk = e >> 2, c = e & 3;
            float s = 0.f;
#pragma unroll
            for (int w = 0; w < NWARPS; ++w) s += spart[w][kk][c];
            g_part[bid * NENT + e] = s;
        }
        if (tid == 0) {
            float s = 0.f;
#pragma unroll
            for (int w = 0; w < NWARPS; ++w) s += snp[w];
            g_part[bid * NENT + 512] = s;
        }
    }
    gbar(&g_bar[1], NBLOCKS);

    // ---------------- P3: fold partials across blocks -> g_coef ----------------
    {
        const int e = bid + NBLOCKS * wid;
        if (wid < 4 && e < NENT) {
            float s = 0.f;
            for (int b = lane; b < NBLOCKS; b += 32)
                s += g_part[b * NENT + e];
#pragma unroll
            for (int o = 16; o > 0; o >>= 1)
                s += __shfl_down_sync(0xffffffffu, s, o);
            if (lane == 0) g_coef[e] = s;
        }
    }
    gbar(&g_bar[2], NBLOCKS);

    // ---------------- P4: coefficients + CDF points + partial AUC ----------------
    __shared__ float sisp[N_K], sicp[N_K], sisn[N_K], sicn[N_K];
    __shared__ float ptp[NWARPS + 1], ptn[NWARPS + 1];  // (+1 unused pad)
    if (tid < N_K) {
        const float EPS = 1.1920929e-7f;
        const int k = tid + 1;
        const float tpk = TWO_PI * (float)k;
        const float npos = g_coef[512];
        const float nneg = (float)N_SAMPLES - npos;

        // sinc correction for uniform-within-bin
        const float x = (float)k * (3.14159265358979f / (float)BINS);
        const float snc = __sinf(x) / x;

        const float St = g_coef[tid * 4 + 0];
        const float Ct = g_coef[tid * 4 + 1];
        const float Sp = g_coef[tid * 4 + 2];
        const float Cp = g_coef[tid * 4 + 3];

        const float ps  = (npos < EPS) ? 0.f : (Sp * snc) / fmaxf(npos, EPS);
        const float pc  = (npos < EPS) ? 0.f : (Cp * snc) / fmaxf(npos, EPS);
        const float nsn = (nneg < EPS) ? 0.f : ((St - Sp) * snc) / fmaxf(nneg, EPS);
        const float ncn = (nneg < EPS) ? 0.f : ((Ct - Cp) * snc) / fmaxf(nneg, EPS);

        sisp[tid] =  pc / tpk;
        sicp[tid] = -ps / tpk;
        sisn[tid] =  ncn / tpk;
        sicn[tid] = -nsn / tpk;
    }
    __syncthreads();

    // Block handles intervals [i0, i1); needs points i0 .. i1 (<= 8 points).
    const int i0 = (bid * N_INTERVALS) / NBLOCKS;
    const int i1 = ((bid + 1) * N_INTERVALS) / NBLOCKS;
    const int npts = i1 - i0 + 1;
    {
        const int j = i0 + wid;                   // point index this warp computes
        if (wid < npts) {
            float vp, vn;
            if (j == 0)            { vp = 1.f; vn = 1.f; }
            else if (j == 1025)    { vp = 0.f; vn = 0.f; }
            else {
                const float thr = (float)(j - 1) / 1023.0f;
                float cdfp = 0.f, cdfn = 0.f;
#pragma unroll
                for (int i = 0; i < 4; ++i) {
                    const int k = lane + i * 32;
                    const float tpk = TWO_PI * (float)(k + 1);
                    float s, c;
                    __sincosf(thr * tpk, &s, &c);
                    cdfp = fmaf(s, sisp[k], fmaf(c, sicp[k], cdfp));
                    cdfn = fmaf(s, sisn[k], fmaf(c, sicn[k], cdfn));
                }
#pragma unroll
                for (int o = 16; o > 0; o >>= 1) {
                    cdfp += __shfl_down_sync(0xffffffffu, cdfp, o);
                    cdfn += __shfl_down_sync(0xffffffffu, cdfn, o);
                }
                vp = 1.0f - 0.5f * (cdfp + 0.5f);
                vn = 1.0f - 0.5f * (cdfn + 0.5f);
            }
            if (lane == 0) { ptp[wid] = vp; ptn[wid] = vn; }
        }
    }
    __syncthreads();
    if (tid == 0) {
        float tp = 0.f, tn = 0.f;
        for (int i = 0; i < npts - 1; ++i) {
            tp = fmaf(ptp[i], ptn[i] - ptn[i + 1], tp);
            tn = fmaf(ptn[i], ptp[i + 1] - ptp[i], tn);
        }
        g_aucA[bid] = tp;
        g_aucB[bid] = tn;
    }

    // ---------------- completion counter; last block finishes ----------------
    __syncthreads();
    __shared__ unsigned int is_last;
    if (tid == 0) {
        unsigned int old;
        asm volatile("atom.release.gpu.global.add.u32 %0, [%1], %2;"
                     : "=r"(old) : "l"(&g_bar[3]), "r"(1u) : "memory");
        is_last = (old == NBLOCKS - 1) ? 1u : 0u;
    }
    __syncthreads();
    if (!is_last) return;
    if (tid == 0) {
        unsigned int v;
        asm volatile("ld.acquire.gpu.global.u32 %0, [%1];"
                     : "=r"(v) : "l"(&g_bar[3]) : "memory");
        (void)v;
    }
    __syncthreads();

    if (wid == 0) {
        float a = 0.f, b = 0.f;
        for (int i = lane; i < NBLOCKS; i += 32) { a += g_aucA[i]; b += g_aucB[i]; }
#pragma unroll
        for (int o = 16; o > 0; o >>= 1) {
            a += __shfl_down_sync(0xffffffffu, a, o);
            b += __shfl_down_sync(0xffffffffu, b, o);
        }
        if (lane == 0) {
            out[0] = 0.5f * (a + (1.0f + b));
            g_bar[0] = 0; g_bar[1] = 0; g_bar[2] = 0; g_bar[3] = 0;
        }
    }
}

extern "C" void kernel_launch(void* const* d_in, const int* in_sizes, int n_in,
                              void* d_out, int out_size)
{
    (void)in_sizes; (void)n_in; (void)out_size;
    const float4* scores4  = (const float4*)d_in[0];
    const uint4*  targets4 = (const uint4*)d_in[1];
    float* out = (float*)d_out;

    fused_kernel<<<NBLOCKS, THREADS>>>(scores4, targets4, out);
}

// round 10
// speedup vs baseline: 1.7254x; 1.1193x over previous
#include <cuda_runtime.h>
#include <math.h>

#define N_SAMPLES 262144
#define N_QUADS   (N_SAMPLES / 4)                 // 65536
#define N_K       128
#define N_STEPS   1024
#define BINS      4096
#define DENOM     (2 * BINS)                      // 8192: angle = 2pi*q/DENOM
#define NBLOCKS   148                             // <= SM count -> co-resident
#define THREADS   512
#define NWARPS    (THREADS / 32)                  // 16
#define N_INTERVALS 1025
#define TWO_PI    6.2831855f

typedef unsigned long long u64;

// Histogram: per bin, high 32 = n_total, low 32 = n_positive. Zero-initialized
// at load; each launch restores zeros in P3 (after the last read).
__device__ u64   g_hist[BINS];
// Coefficients: [k-1][4] = (tot_s, tot_c, pos_s, pos_c), plus [512] = npos
__device__ float g_coef[4 * N_K + 1];
// Per-block AUC partial sums
__device__ float g_aucA[NBLOCKS], g_aucB[NBLOCKS];
// Barrier / completion counters (self-reset each launch)
__device__ unsigned int g_bar[3] = {0, 0, 0};

// Light grid barrier: release-add + acquire-poll (no threadfence / L1 flush).
__device__ __forceinline__ void gbar(unsigned int* cnt, unsigned int target)
{
    __syncthreads();
    if (threadIdx.x == 0) {
        unsigned int old;
        asm volatile("atom.release.gpu.global.add.u32 %0, [%1], %2;"
                     : "=r"(old) : "l"(cnt), "r"(1u) : "memory");
        unsigned int v;
        do {
            asm volatile("ld.acquire.gpu.global.u32 %0, [%1];"
                         : "=r"(v) : "l"(cnt) : "memory");
        } while (v < target);
    }
    __syncthreads();
}

// ---------------------------------------------------------------------------
// Single fused kernel, 148 blocks x 512 threads (1/SM, co-resident).
//  P1: histogram via one packed u64 atomic per sample          -> barrier A
//  P2: harmonic-per-block DFT: block b<128 sums all 4096 bins for harmonic
//      b+1 and writes g_coef[4b..4b+3]; block 128 sums npos    -> barrier B
//  P3: zero own hist slice; coefficients + CDF points (1/warp) + local
//      partial AUC -> counter; last block folds 148 partials -> out.
// ---------------------------------------------------------------------------
__global__ void __launch_bounds__(THREADS, 1)
fused_kernel(const float4* __restrict__ scores4, const uint4* __restrict__ targets4,
             float* __restrict__ out)
{
    const int bid  = blockIdx.x;
    const int tid  = threadIdx.x;
    const int lane = tid & 31, wid = tid >> 5;

    // ---------------- P1: histogram ----------------
    {
        const int qs = (bid * N_QUADS) / NBLOCKS;
        const int qe = ((bid + 1) * N_QUADS) / NBLOCKS;
        for (int i = qs + tid; i < qe; i += THREADS) {
            const float4 sv = scores4[i];
            const uint4  tv = targets4[i];
            const float scs[4] = {sv.x, sv.y, sv.z, sv.w};
            const unsigned ms[4] = {tv.x, tv.y, tv.z, tv.w};
#pragma unroll
            for (int e = 0; e < 4; ++e) {
                int b = (int)(scs[e] * (float)BINS);
                b = (b > BINS - 1) ? (BINS - 1) : ((b < 0) ? 0 : b);
                const u64 add = (1ull << 32) | (u64)(ms[e] ? 1u : 0u);
                atomicAdd(&g_hist[b], add);
            }
        }
    }
    gbar(&g_bar[0], NBLOCKS);

    // ---------------- P2: harmonic-per-block DFT ----------------
    __shared__ float rsum[NWARPS][4];
    if (bid < N_K) {
        const int k = bid + 1;
        float ts = 0.f, tc = 0.f, ps = 0.f, pc = 0.f;
#pragma unroll
        for (int j = 0; j < BINS / THREADS; ++j) {
            const int bin = tid + j * THREADS;
            const u64 h = g_hist[bin];
            const float nt = (float)(unsigned)(h >> 32);
            const float np = (float)(unsigned)(h & 0xffffffffu);
            const int q = (k * (2 * bin + 1)) & (DENOM - 1);  // exact mod 2pi
            const float ang = (float)q * (TWO_PI / (float)DENOM);
            float s, c;
            __sincosf(ang, &s, &c);
            ts = fmaf(nt, s, ts);
            tc = fmaf(nt, c, tc);
            ps = fmaf(np, s, ps);
            pc = fmaf(np, c, pc);
        }
#pragma unroll
        for (int o = 16; o > 0; o >>= 1) {
            ts += __shfl_down_sync(0xffffffffu, ts, o);
            tc += __shfl_down_sync(0xffffffffu, tc, o);
            ps += __shfl_down_sync(0xffffffffu, ps, o);
            pc += __shfl_down_sync(0xffffffffu, pc, o);
        }
        if (lane == 0) {
            rsum[wid][0] = ts; rsum[wid][1] = tc;
            rsum[wid][2] = ps; rsum[wid][3] = pc;
        }
        __syncthreads();
        if (tid < 4) {
            float s = 0.f;
#pragma unroll
            for (int w = 0; w < NWARPS; ++w) s += rsum[w][tid];
            g_coef[4 * bid + tid] = s;
        }
    } else if (bid == N_K) {
        float np = 0.f;
#pragma unroll
        for (int j = 0; j < BINS / THREADS; ++j) {
            const u64 h = g_hist[tid + j * THREADS];
            np += (float)(unsigned)(h & 0xffffffffu);
        }
#pragma unroll
        for (int o = 16; o > 0; o >>= 1)
            np += __shfl_down_sync(0xffffffffu, np, o);
        if (lane == 0) rsum[wid][0] = np;
        __syncthreads();
        if (tid == 0) {
            float s = 0.f;
#pragma unroll
            for (int w = 0; w < NWARPS; ++w) s += rsum[w][0];
            g_coef[4 * N_K] = s;
        }
    }
    gbar(&g_bar[1], NBLOCKS);

    // ---------------- P3: zero hist, coefficients, CDF, partial AUC ----------------
    // zero own slice (hist is dead after barrier B)
    {
        const int zs = (bid * BINS) / NBLOCKS;
        const int ze = ((bid + 1) * BINS) / NBLOCKS;
        for (int b = zs + tid; b < ze; b += THREADS) g_hist[b] = 0ull;
    }

    __shared__ float sisp[N_K], sicp[N_K], sisn[N_K], sicn[N_K];
    __shared__ float ptp[9], ptn[9];
    if (tid < N_K) {
        const float EPS = 1.1920929e-7f;
        const int k = tid + 1;
        const float tpk = TWO_PI * (float)k;
        const float npos = g_coef[4 * N_K];
        const float nneg = (float)N_SAMPLES - npos;

        // sinc correction for uniform-within-bin
        const float x = (float)k * (3.14159265358979f / (float)BINS);
        const float snc = __sinf(x) / x;

        const float St = g_coef[tid * 4 + 0];
        const float Ct = g_coef[tid * 4 + 1];
        const float Sp = g_coef[tid * 4 + 2];
        const float Cp = g_coef[tid * 4 + 3];

        const float ps  = (npos < EPS) ? 0.f : (Sp * snc) / fmaxf(npos, EPS);
        const float pc  = (npos < EPS) ? 0.f : (Cp * snc) / fmaxf(npos, EPS);
        const float nsn = (nneg < EPS) ? 0.f : ((St - Sp) * snc) / fmaxf(nneg, EPS);
        const float ncn = (nneg < EPS) ? 0.f : ((Ct - Cp) * snc) / fmaxf(nneg, EPS);

        sisp[tid] =  pc / tpk;
        sicp[tid] = -ps / tpk;
        sisn[tid] =  ncn / tpk;
        sicn[tid] = -nsn / tpk;
    }
    __syncthreads();

    // Block handles intervals [i0, i1); needs points i0 .. i1 (<= 8 points).
    const int i0 = (bid * N_INTERVALS) / NBLOCKS;
    const int i1 = ((bid + 1) * N_INTERVALS) / NBLOCKS;
    const int npts = i1 - i0 + 1;
    {
        const int j = i0 + wid;                   // point index this warp computes
        if (wid < npts) {
            float vp, vn;
            if (j == 0)            { vp = 1.f; vn = 1.f; }
            else if (j == 1025)    { vp = 0.f; vn = 0.f; }
            else {
                const float thr = (float)(j - 1) / 1023.0f;
                float cdfp = 0.f, cdfn = 0.f;
#pragma unroll
                for (int i = 0; i < 4; ++i) {
                    const int k = lane + i * 32;
                    const float tpk = TWO_PI * (float)(k + 1);
                    float s, c;
                    __sincosf(thr * tpk, &s, &c);
                    cdfp = fmaf(s, sisp[k], fmaf(c, sicp[k], cdfp));
                    cdfn = fmaf(s, sisn[k], fmaf(c, sicn[k], cdfn));
                }
#pragma unroll
                for (int o = 16; o > 0; o >>= 1) {
                    cdfp += __shfl_down_sync(0xffffffffu, cdfp, o);
                    cdfn += __shfl_down_sync(0xffffffffu, cdfn, o);
                }
                vp = 1.0f - 0.5f * (cdfp + 0.5f);
                vn = 1.0f - 0.5f * (cdfn + 0.5f);
            }
            if (lane == 0) { ptp[wid] = vp; ptn[wid] = vn; }
        }
    }
    __syncthreads();
    if (tid == 0) {
        float tp = 0.f, tn = 0.f;
        for (int i = 0; i < npts - 1; ++i) {
            tp = fmaf(ptp[i], ptn[i] - ptn[i + 1], tp);
            tn = fmaf(ptn[i], ptp[i + 1] - ptp[i], tn);
        }
        g_aucA[bid] = tp;
        g_aucB[bid] = tn;
    }

    // ---------------- completion counter; last block finishes ----------------
    __syncthreads();
    __shared__ unsigned int is_last;
    if (tid == 0) {
        unsigned int old;
        asm volatile("atom.release.gpu.global.add.u32 %0, [%1], %2;"
                     : "=r"(old) : "l"(&g_bar[2]), "r"(1u) : "memory");
        is_last = (old == NBLOCKS - 1) ? 1u : 0u;
    }
    __syncthreads();
    if (!is_last) return;
    if (tid == 0) {
        unsigned int v;
        asm volatile("ld.acquire.gpu.global.u32 %0, [%1];"
                     : "=r"(v) : "l"(&g_bar[2]) : "memory");
        (void)v;
    }
    __syncthreads();

    if (wid == 0) {
        float a = 0.f, b = 0.f;
        for (int i = lane; i < NBLOCKS; i += 32) { a += g_aucA[i]; b += g_aucB[i]; }
#pragma unroll
        for (int o = 16; o > 0; o >>= 1) {
            a += __shfl_down_sync(0xffffffffu, a, o);
            b += __shfl_down_sync(0xffffffffu, b, o);
        }
        if (lane == 0) {
            out[0] = 0.5f * (a + (1.0f + b));
            g_bar[0] = 0; g_bar[1] = 0; g_bar[2] = 0;
        }
    }
}

extern "C" void kernel_launch(void* const* d_in, const int* in_sizes, int n_in,
                              void* d_out, int out_size)
{
    (void)in_sizes; (void)n_in; (void)out_size;
    const float4* scores4  = (const float4*)d_in[0];
    const uint4*  targets4 = (const uint4*)d_in[1];
    float* out = (float*)d_out;

    fused_kernel<<<NBLOCKS, THREADS>>>(scores4, targets4, out);
}